// round 16
// baseline (speedup 1.0000x reference)
#include <cuda_runtime.h>
#include <cuda_fp16.h>
#include <math.h>
#include <stdint.h>

#define B_ 32
#define T_ 1024
#define D_ 512
#define H_ 2048
#define E_ 8

#define BM 128
#define BN 128
#define BK 64                    // halves per k-tile (4 x k16 mma steps), 128B rows
#define STAGES 3

#define A_BYTES (BM * 128)                    // 16384
#define B_BYTES (BN * 128)                    // 16384
#define STAGE_BYTES (A_BYTES + B_BYTES)       // 32768
#define SMEMSZ (STAGES * STAGE_BYTES)         // 98304  (dynamic only!)

// mega kernel bid layout
#define NB_POOL 256
#define NB_W1T  2048
#define NB_W2T  2048
#define NB_G1   (16 * 8 * 64)                 // 8192
#define NB_G2   (4 * 8 * 32)                  // 1024
#define OFF_W1T (NB_POOL)
#define OFF_W2T (OFF_W1T + NB_W1T)
#define OFF_G1  (OFF_W2T + NB_W2T)
#define OFF_G2  (OFF_G1 + NB_G1)
#define NB_ALL  (OFF_G2 + NB_G2)

// ---------------------------------------------------------------------------
// scratch (device globals — no allocation allowed)
// ---------------------------------------------------------------------------
__device__ int      g_eidx[B_][2];
__device__ float    g_prob[B_][2];
__device__ float    g_pool[B_][8][D_];
__device__ unsigned g_cnt[B_][8];                    // gemm1->gemm2 (target 32)
__device__ unsigned g_w1c[E_ * 16];                  // w1t slices   (target 16)
__device__ unsigned g_w2c[E_ * 4];                   // w2t slices   (target 64)
__device__ unsigned g_poolc[B_];                     // pool blocks  (target 8)
__device__ unsigned g_gatef[B_];                     // gate ready flag
__device__ __half   g_xh[(size_t)B_ * T_ * D_];      // fp16 x
__device__ __half   g_w1t[(size_t)E_ * H_ * D_];     // w1^T [E][H][D] fp16
__device__ __half   g_w2t[(size_t)E_ * D_ * H_];     // w2^T [E][D][H] fp16
__device__ __half   g_h[(size_t)B_ * T_ * (2 * H_)]; // p*silu(x@w1+b1) fp16

// ---------------------------------------------------------------------------
// helpers
// ---------------------------------------------------------------------------
__device__ __forceinline__ uint32_t smem_u32(const void* p) {
    uint32_t a;
    asm("{ .reg .u64 t; cvta.to.shared.u64 t, %1; cvt.u32.u64 %0, t; }" : "=r"(a) : "l"(p));
    return a;
}
__device__ __forceinline__ void cp16(uint32_t dst, const void* src) {
    asm volatile("cp.async.cg.shared.global [%0], [%1], 16;" :: "r"(dst), "l"(src));
}
__device__ __forceinline__ void cp_commit() {
    asm volatile("cp.async.commit_group;" ::: "memory");
}
template <int N>
__device__ __forceinline__ void cp_wait() {
    asm volatile("cp.async.wait_group %0;" :: "n"(N) : "memory");
}
__device__ __forceinline__ void ldsm_x4(unsigned& r0, unsigned& r1, unsigned& r2,
                                        unsigned& r3, uint32_t addr) {
    asm volatile("ldmatrix.sync.aligned.m8n8.x4.shared.b16 {%0,%1,%2,%3}, [%4];"
        : "=r"(r0), "=r"(r1), "=r"(r2), "=r"(r3) : "r"(addr));
}
__device__ __forceinline__ void ldsm_x2(unsigned& r0, unsigned& r1, uint32_t addr) {
    asm volatile("ldmatrix.sync.aligned.m8n8.x2.shared.b16 {%0,%1}, [%2];"
        : "=r"(r0), "=r"(r1) : "r"(addr));
}
__device__ __forceinline__ void mma_f16(float* d, const unsigned* a, const unsigned* b) {
    asm volatile(
        "mma.sync.aligned.m16n8k16.row.col.f32.f16.f16.f32 "
        "{%0,%1,%2,%3}, {%4,%5,%6,%7}, {%8,%9}, {%0,%1,%2,%3};\n"
        : "+f"(d[0]), "+f"(d[1]), "+f"(d[2]), "+f"(d[3])
        : "r"(a[0]), "r"(a[1]), "r"(a[2]), "r"(a[3]), "r"(b[0]), "r"(b[1]));
}
__device__ __forceinline__ void spin_ge(const unsigned* p, unsigned target) {
    unsigned v;
    do {
        asm volatile("ld.global.acquire.gpu.u32 %0, [%1];" : "=r"(v) : "l"(p) : "memory");
        if (v < target) __nanosleep(128);
    } while (v < target);
}
// release-ordered counter increment (pairs with ld.acquire spins; avoids MEMBAR.GPU)
__device__ __forceinline__ void release_add(unsigned* p, unsigned v) {
    asm volatile("red.release.gpu.global.add.u32 [%0], %1;" :: "l"(p), "r"(v) : "memory");
}

// ---------------------------------------------------------------------------
// reset kernel (tiny; kernel boundary orders it before mega)
// ---------------------------------------------------------------------------
__global__ void reset_kernel() {
    const int i = threadIdx.x;   // 512 threads
    if (i < B_ * 8)  ((unsigned*)g_cnt)[i] = 0u;
    if (i < E_ * 16) g_w1c[i] = 0u;
    if (i < E_ * 4)  g_w2c[i] = 0u;
    if (i < B_)      { g_poolc[i] = 0u; g_gatef[i] = 0u; }
}

// ---------------------------------------------------------------------------
// GEMM core macros: 256 threads, 8 warps 2(m)x4(n), warp tile 64x32
// A/B tiles: 128 rows x 128B, XOR-swizzled: chunk_phys = chunk ^ (row&7)
// ---------------------------------------------------------------------------
#define ISSUE_STAGE_A(slot, A_SRC) do {                                        \
    const uint32_t _as = sm_base + (slot) * STAGE_BYTES;                       \
    _Pragma("unroll")                                                          \
    for (int _i = 0; _i < 4; _i++) {                                           \
        const int _c = _i * 256 + tid;                                         \
        const int _r = _c >> 3, _lc = _c & 7;                                  \
        cp16(_as + _r * 128 + ((_lc ^ (_r & 7)) << 4), (A_SRC(_r, _lc)));      \
    }                                                                          \
} while (0)

#define ISSUE_STAGE_B(slot, B_SRC) do {                                        \
    const uint32_t _bs = sm_base + (slot) * STAGE_BYTES + A_BYTES;             \
    _Pragma("unroll")                                                          \
    for (int _i = 0; _i < 4; _i++) {                                           \
        const int _c = _i * 256 + tid;                                         \
        const int _r = _c >> 3, _lc = _c & 7;                                  \
        cp16(_bs + _r * 128 + ((_lc ^ (_r & 7)) << 4), (B_SRC(_r, _lc)));      \
    }                                                                          \
} while (0)

#define ISSUE_STAGE(slot, A_SRC, B_SRC) do {                                   \
    ISSUE_STAGE_A(slot, A_SRC);                                                \
    ISSUE_STAGE_B(slot, B_SRC);                                                \
} while (0)

#define COMPUTE_STAGE(slot) do {                                               \
    const uint32_t _ab = sm_base + (slot) * STAGE_BYTES;                       \
    const uint32_t _bb = _ab + A_BYTES;                                        \
    _Pragma("unroll")                                                          \
    for (int ks = 0; ks < 4; ks++) {                                           \
        unsigned af[4][4], bf[4][2];                                           \
        _Pragma("unroll")                                                      \
        for (int mt = 0; mt < 4; mt++)                                         \
            ldsm_x4(af[mt][0], af[mt][1], af[mt][2], af[mt][3],                \
                    _ab + arow_off + mt * 2048 + (((2 * ks + ac) ^ sxor) << 4)); \
        _Pragma("unroll")                                                      \
        for (int nt = 0; nt < 4; nt++)                                         \
            ldsm_x2(bf[nt][0], bf[nt][1],                                      \
                    _bb + brow_off + nt * 1024 + (((2 * ks + bc) ^ sxor) << 4)); \
        _Pragma("unroll")                                                      \
        for (int mt = 0; mt < 4; mt++)                                         \
            _Pragma("unroll")                                                  \
            for (int nt = 0; nt < 4; nt++)                                     \
                mma_f16(acc[mt][nt], af[mt], bf[nt]);                          \
    }                                                                          \
} while (0)

// mainloop shared by both gemms (prologue handled by caller)
#define GEMM_MAINLOOP(NK, A_SRC, B_SRC) do {                                   \
    for (int kt = 0; kt < (NK); kt++) {                                        \
        cp_wait<STAGES - 2>();                                                 \
        __syncthreads();                                                       \
        const int pf = kt + STAGES - 1;                                        \
        if (pf < (NK)) {                                                       \
            const int kk = pf;                                                 \
            ISSUE_STAGE(pf % STAGES, A_SRC, B_SRC);                            \
        }                                                                      \
        cp_commit();                                                           \
        COMPUTE_STAGE(kt % STAGES);                                            \
    }                                                                          \
} while (0)

#define GEMM_PIPELINE(NK, A_SRC, B_SRC) do {                                   \
    _Pragma("unroll")                                                          \
    for (int s = 0; s < STAGES - 1; s++) {                                     \
        const int kk = s;                                                      \
        ISSUE_STAGE(s, A_SRC, B_SRC);                                          \
        cp_commit();                                                           \
    }                                                                          \
    GEMM_MAINLOOP(NK, A_SRC, B_SRC);                                           \
} while (0)

#define LANE_OFFS()                                                            \
    const int wm = (warp & 1) * 64;                                            \
    const int wn = (warp >> 1) * 32;                                           \
    const uint32_t arow_off = (uint32_t)(wm + (lane & 15)) * 128;              \
    const uint32_t ac = (uint32_t)(lane >> 4);                                 \
    const uint32_t brow_off = (uint32_t)(wn + (lane & 7)) * 128;               \
    const uint32_t bc = (uint32_t)((lane >> 3) & 1);                           \
    const uint32_t sxor = (uint32_t)(lane & 7);

// ---------------------------------------------------------------------------
// MEGA kernel: [pool+gate | w1t | w2t | gemm1 | gemm2]  (dynamic smem ONLY)
// ---------------------------------------------------------------------------
__global__ __launch_bounds__(256, 2) void mega_kernel(
        const float* __restrict__ x,  const float* __restrict__ gw,
        const float* __restrict__ gb, const float* __restrict__ w1,
        const float* __restrict__ b1, const float* __restrict__ w2,
        const float* __restrict__ b2, float* __restrict__ out,
        float* __restrict__ out_logits) {
    extern __shared__ char smem[];
    const int bid = blockIdx.x;
    const int tid = threadIdx.x;

    if (bid < NB_POOL) {
        // -------- pool + x->fp16; 8th block per batch computes gate --------
        const int b = bid >> 3, ch = bid & 7;
        const size_t rbase = ((size_t)b * T_ + (size_t)ch * 128) * D_;
        #pragma unroll
        for (int half = 0; half < 2; half++) {
            const int d = tid + half * 256;
            float s = 0.f;
            for (int t = 0; t < 128; t++) {
                float v = x[rbase + (size_t)t * D_ + d];
                s += v;
                g_xh[rbase + (size_t)t * D_ + d] = __float2half_rn(v);
            }
            g_pool[b][ch][d] = s;
        }
        int* is_last = (int*)smem;
        __syncthreads();
        if (tid == 0) {
            __threadfence();
            *is_last = (atomicAdd(&g_poolc[b], 1u) == 7u) ? 1 : 0;
        }
        __syncthreads();
        if (*is_last) {
            __threadfence();
            float* pooled = (float*)smem + 16;     // 512 floats
            float* logits = pooled + 512;          // 8 floats
            #pragma unroll
            for (int half = 0; half < 2; half++) {
                const int d = tid + half * 256;
                float s = 0.f;
                #pragma unroll
                for (int c = 0; c < 8; c++) s += g_pool[b][c][d];
                pooled[d] = s * (1.0f / (float)T_);
            }
            __syncthreads();
            const int w = tid >> 5, lane = tid & 31;
            if (w < E_) {
                float acc = 0.f;
                for (int j = lane; j < D_; j += 32)
                    acc += pooled[j] * gw[(size_t)j * E_ + w];
                #pragma unroll
                for (int o = 16; o > 0; o >>= 1)
                    acc += __shfl_xor_sync(0xffffffffu, acc, o);
                if (lane == 0) logits[w] = acc + gb[w];
            }
            __syncthreads();
            if (tid == 0) {
                int i0 = 0; float l0 = logits[0];
                #pragma unroll
                for (int e = 1; e < E_; e++) if (logits[e] > l0) { l0 = logits[e]; i0 = e; }
                int i1 = -1; float l1 = -1e30f;
                #pragma unroll
                for (int e = 0; e < E_; e++)
                    if (e != i0 && logits[e] > l1) { l1 = logits[e]; i1 = e; }
                float e1 = expf(l1 - l0);
                float inv = 1.0f / (1.0f + e1);
                g_eidx[b][0] = i0; g_eidx[b][1] = i1;
                g_prob[b][0] = inv; g_prob[b][1] = e1 * inv;
                #pragma unroll
                for (int e = 0; e < E_; e++) out_logits[b * E_ + e] = logits[e];
                release_add(&g_gatef[b], 1u);
            }
        }
        return;
    }
    if (bid < OFF_W2T) {
        // -------- w1 transpose: [E][D][H] -> [E][H][D]  (dyn smem tile) ----
        float* tile = (float*)smem;                 // [64][65]
        const int idx = bid - OFF_W1T;
        const int e = idx >> 8, cx = idx & 31, cy = (idx >> 5) & 7;
        const float* S = w1 + (size_t)e * D_ * H_;
        __half* Dp = g_w1t + (size_t)e * H_ * D_;
        const int r0 = cy * 64, c0 = cx * 64;
        const int tx = tid & 63, ty = tid >> 6;     // ty 0..3
        #pragma unroll
        for (int i = 0; i < 16; i++) {
            const int row = ty + i * 4;
            tile[row * 65 + tx] = S[(size_t)(r0 + row) * H_ + c0 + tx];
        }
        __syncthreads();
        #pragma unroll
        for (int i = 0; i < 16; i++) {
            const int row = ty + i * 4;
            Dp[(size_t)(c0 + row) * D_ + r0 + tx] = __float2half_rn(tile[tx * 65 + row]);
        }
        __syncthreads();
        if (tid == 0) release_add(&g_w1c[e * 16 + (cx >> 1)], 1u);
        return;
    }
    if (bid < OFF_G1) {
        // -------- w2 transpose: [E][H][D] -> [E][D][H] ----------------------
        float* tile = (float*)smem;
        const int idx = bid - OFF_W2T;
        const int e = idx >> 8, cx = idx & 7, cy = (idx >> 3) & 31;
        const float* S = w2 + (size_t)e * H_ * D_;
        __half* Dp = g_w2t + (size_t)e * D_ * H_;
        const int r0 = cy * 64, c0 = cx * 64;
        const int tx = tid & 63, ty = tid >> 6;
        #pragma unroll
        for (int i = 0; i < 16; i++) {
            const int row = ty + i * 4;
            tile[row * 65 + tx] = S[(size_t)(r0 + row) * D_ + c0 + tx];
        }
        __syncthreads();
        #pragma unroll
        for (int i = 0; i < 16; i++) {
            const int row = ty + i * 4;
            Dp[(size_t)(c0 + row) * H_ + r0 + tx] = __float2half_rn(tile[tx * 65 + row]);
        }
        __syncthreads();
        if (tid == 0) release_add(&g_w2c[e * 4 + (cx >> 1)], 1u);
        return;
    }

    // ======================= GEMM paths =======================
    const uint32_t sm_base = smem_u32(smem);
    const int warp = tid >> 5, lane = tid & 31;
    LANE_OFFS();
    const int g = lane >> 2, t4 = lane & 3;

    float acc[4][4][4];
    #pragma unroll
    for (int i = 0; i < 4; i++)
        #pragma unroll
        for (int j = 0; j < 4; j++)
            #pragma unroll
            for (int r = 0; r < 4; r++) acc[i][j][r] = 0.f;

    if (bid < OFF_G2) {
        // =============== GEMM1 ===============
        const int v = bid - OFF_G1;
        const int xt = v & 15, yt = (v >> 4) & 7, bz = v >> 7;
        const int b = bz >> 1, slot = bz & 1;
        const int m0 = yt * BM, n0 = xt * BN;

        const __half* Ag = g_xh + ((size_t)b * T_ + m0) * D_;
        #define A1(r, c) (Ag + (size_t)(r) * D_ + kk * BK + (c) * 8)

        // prefetch A stages 0,1 BEFORE dependency spins (A needs no gate/e)
        {
            { const int kk = 0; ISSUE_STAGE_A(0, A1); }
            { const int kk = 1; ISSUE_STAGE_A(1, A1); }
        }

        if (tid == 0) spin_ge(&g_gatef[b], 1u);
        __syncthreads();
        const int e = g_eidx[b][slot];
        const float p = g_prob[b][slot];
        if (tid == 0) spin_ge(&g_w1c[e * 16 + xt], 16u);
        __syncthreads();

        const __half* Bg = g_w1t + ((size_t)e * H_ + n0) * D_;
        #define B1(r, c) (Bg + (size_t)(r) * D_ + kk * BK + (c) * 8)

        // finish prologue: B for stages 0,1 (group0 = A0,A1,B0; group1 = B1)
        { const int kk = 0; ISSUE_STAGE_B(0, B1); }
        cp_commit();
        { const int kk = 1; ISSUE_STAGE_B(1, B1); }
        cp_commit();

        GEMM_MAINLOOP(D_ / BK, A1, B1);      // 8 k-tiles
        #undef A1
        #undef B1

        const float* brow = b1 + (size_t)e * H_ + n0;
        __half* Hb = g_h + ((size_t)b * T_ + m0) * (2 * H_) + (size_t)slot * H_ + n0;
        #pragma unroll
        for (int mt = 0; mt < 4; mt++) {
            #pragma unroll
            for (int nt = 0; nt < 4; nt++) {
                #pragma unroll
                for (int half = 0; half < 2; half++) {
                    const int row = wm + mt * 16 + g + half * 8;
                    const int col = wn + nt * 8 + t4 * 2;
                    float v0 = acc[mt][nt][half * 2 + 0] + brow[col];
                    float v1 = acc[mt][nt][half * 2 + 1] + brow[col + 1];
                    v0 = p * v0 * (1.0f / (1.0f + __expf(-v0)));
                    v1 = p * v1 * (1.0f / (1.0f + __expf(-v1)));
                    *(__half2*)&Hb[(size_t)row * (2 * H_) + col] =
                        __floats2half2_rn(v0, v1);
                }
            }
        }
        __syncthreads();
        if (tid == 0) release_add(&g_cnt[b][yt], 1u);
    } else {
        // =============== GEMM2 ===============
        const int r2 = bid - OFF_G2;
        const int xt = r2 & 3, yt = (r2 >> 2) & 7, b = r2 >> 5;
        const int m0 = yt * BM, n0 = xt * BN;

        // gate + w2t are ready early; the g_cnt producer spin is the long one.
        if (tid == 0) spin_ge(&g_gatef[b], 1u);
        __syncthreads();
        const int e0 = g_eidx[b][0], e1 = g_eidx[b][1];
        const float p0 = g_prob[b][0], p1 = g_prob[b][1];
        if (tid == 0) {
            spin_ge(&g_w2c[e0 * 4 + xt], 64u);
            spin_ge(&g_w2c[e1 * 4 + xt], 64u);
        }
        __syncthreads();

        const __half* Ag  = g_h + ((size_t)b * T_ + m0) * (2 * H_);
        const __half* Bg0 = g_w2t + ((size_t)e0 * D_ + n0) * H_;
        const __half* Bg1 = g_w2t + ((size_t)e1 * D_ + n0) * H_;

        #define A2(r, c) (Ag + (size_t)(r) * (2 * H_) + kk * BK + (c) * 8)
        #define B2(r, c) ((kk < 32 ? Bg0 : Bg1) + (size_t)(r) * H_ + (kk & 31) * BK + (c) * 8)

        // prefetch B stages 0,1 BEFORE the producer spin (B needs no g_h)
        { const int kk = 0; ISSUE_STAGE_B(0, B2); }
        { const int kk = 1; ISSUE_STAGE_B(1, B2); }

        if (tid == 0) spin_ge(&g_cnt[b][yt], 32u);
        __syncthreads();

        // finish prologue: A for stages 0,1 (group0 = B0,B1,A0; group1 = A1)
        { const int kk = 0; ISSUE_STAGE_A(0, A2); }
        cp_commit();
        { const int kk = 1; ISSUE_STAGE_A(1, A2); }
        cp_commit();

        GEMM_MAINLOOP((2 * H_) / BK, A2, B2);    // 64 k-tiles
        #undef A2
        #undef B2

        const float* b2r0 = b2 + (size_t)e0 * D_ + n0;
        const float* b2r1 = b2 + (size_t)e1 * D_ + n0;
        const float* xb = x   + ((size_t)b * T_ + m0) * D_ + n0;
        float*       ob = out + ((size_t)b * T_ + m0) * D_ + n0;
        #pragma unroll
        for (int mt = 0; mt < 4; mt++) {
            #pragma unroll
            for (int nt = 0; nt < 4; nt++) {
                #pragma unroll
                for (int half = 0; half < 2; half++) {
                    const int row = wm + mt * 16 + g + half * 8;
                    const int col = wn + nt * 8 + t4 * 2;
                    const float bias0 = p0 * b2r0[col]     + p1 * b2r1[col];
                    const float bias1 = p0 * b2r0[col + 1] + p1 * b2r1[col + 1];
                    const float2 xv = *(const float2*)&xb[(size_t)row * D_ + col];
                    float v0 = acc[mt][nt][half * 2 + 0] + bias0 + xv.x;
                    float v1 = acc[mt][nt][half * 2 + 1] + bias1 + xv.y;
                    *(float2*)&ob[(size_t)row * D_ + col] = make_float2(v0, v1);
                }
            }
        }
    }
}

// ---------------------------------------------------------------------------
extern "C" void kernel_launch(void* const* d_in, const int* in_sizes, int n_in,
                              void* d_out, int out_size) {
    const float* x  = (const float*)d_in[0];
    const float* gw = (const float*)d_in[1];
    const float* gb = (const float*)d_in[2];
    const float* w1 = (const float*)d_in[3];
    const float* b1 = (const float*)d_in[4];
    const float* w2 = (const float*)d_in[5];
    const float* b2 = (const float*)d_in[6];

    float* out = (float*)d_out;
    float* out_logits = out + (size_t)B_ * T_ * D_;

    cudaFuncSetAttribute(mega_kernel, cudaFuncAttributeMaxDynamicSharedMemorySize, SMEMSZ);

    reset_kernel<<<1, 512>>>();
    mega_kernel<<<NB_ALL, 256, SMEMSZ>>>(x, gw, gb, w1, b1, w2, b2, out, out_logits);
}

// round 17
// speedup vs baseline: 1.0082x; 1.0082x over previous
#include <cuda_runtime.h>
#include <cuda_fp16.h>
#include <math.h>
#include <stdint.h>

#define B_ 32
#define T_ 1024
#define D_ 512
#define H_ 2048
#define E_ 8

#define BM 128
#define BN 128
#define BK 64                    // halves per k-tile (4 x k16 mma steps), 128B rows
#define STAGES 3

#define A_BYTES (BM * 128)                    // 16384
#define B_BYTES (BN * 128)                    // 16384
#define STAGE_BYTES (A_BYTES + B_BYTES)       // 32768
#define SMEMSZ (STAGES * STAGE_BYTES)         // 98304  (dynamic only!)

// mega kernel bid layout
#define NB_POOL 256
#define NB_W1T  2048
#define NB_W2T  2048
#define NB_G1   (16 * 8 * 64)                 // 8192
#define NB_G2   (4 * 8 * 32)                  // 1024
#define OFF_W1T (NB_POOL)
#define OFF_W2T (OFF_W1T + NB_W1T)
#define OFF_G1  (OFF_W2T + NB_W2T)
#define OFF_G2  (OFF_G1 + NB_G1)
#define NB_ALL  (OFF_G2 + NB_G2)

// ---------------------------------------------------------------------------
// scratch (device globals — no allocation allowed)
// ---------------------------------------------------------------------------
__device__ int      g_eidx[B_][2];
__device__ float    g_prob[B_][2];
__device__ float    g_pool[B_][8][D_];
__device__ unsigned g_cnt[B_][8];                    // gemm1->gemm2 (target 32)
__device__ unsigned g_w1c[E_ * 16];                  // w1t slices   (target 16)
__device__ unsigned g_w2c[E_ * 4];                   // w2t slices   (target 64)
__device__ unsigned g_poolc[B_];                     // pool blocks  (target 8)
__device__ unsigned g_gatef[B_];                     // gate ready flag
__device__ __half   g_xh[(size_t)B_ * T_ * D_];      // fp16 x
__device__ __half   g_w1t[(size_t)E_ * H_ * D_];     // w1^T [E][H][D] fp16
__device__ __half   g_w2t[(size_t)E_ * D_ * H_];     // w2^T [E][D][H] fp16
__device__ __half   g_h[(size_t)B_ * T_ * (2 * H_)]; // p*silu(x@w1+b1) fp16

// ---------------------------------------------------------------------------
// helpers
// ---------------------------------------------------------------------------
__device__ __forceinline__ uint32_t smem_u32(const void* p) {
    uint32_t a;
    asm("{ .reg .u64 t; cvta.to.shared.u64 t, %1; cvt.u32.u64 %0, t; }" : "=r"(a) : "l"(p));
    return a;
}
__device__ __forceinline__ void cp16(uint32_t dst, const void* src) {
    asm volatile("cp.async.cg.shared.global [%0], [%1], 16;" :: "r"(dst), "l"(src));
}
__device__ __forceinline__ void cp_commit() {
    asm volatile("cp.async.commit_group;" ::: "memory");
}
template <int N>
__device__ __forceinline__ void cp_wait() {
    asm volatile("cp.async.wait_group %0;" :: "n"(N) : "memory");
}
__device__ __forceinline__ void ldsm_x4(unsigned& r0, unsigned& r1, unsigned& r2,
                                        unsigned& r3, uint32_t addr) {
    asm volatile("ldmatrix.sync.aligned.m8n8.x4.shared.b16 {%0,%1,%2,%3}, [%4];"
        : "=r"(r0), "=r"(r1), "=r"(r2), "=r"(r3) : "r"(addr));
}
__device__ __forceinline__ void ldsm_x2(unsigned& r0, unsigned& r1, uint32_t addr) {
    asm volatile("ldmatrix.sync.aligned.m8n8.x2.shared.b16 {%0,%1}, [%2];"
        : "=r"(r0), "=r"(r1) : "r"(addr));
}
__device__ __forceinline__ void mma_f16(float* d, const unsigned* a, const unsigned* b) {
    asm volatile(
        "mma.sync.aligned.m16n8k16.row.col.f32.f16.f16.f32 "
        "{%0,%1,%2,%3}, {%4,%5,%6,%7}, {%8,%9}, {%0,%1,%2,%3};\n"
        : "+f"(d[0]), "+f"(d[1]), "+f"(d[2]), "+f"(d[3])
        : "r"(a[0]), "r"(a[1]), "r"(a[2]), "r"(a[3]), "r"(b[0]), "r"(b[1]));
}
__device__ __forceinline__ void spin_ge(const unsigned* p, unsigned target) {
    unsigned v;
    do {
        asm volatile("ld.global.acquire.gpu.u32 %0, [%1];" : "=r"(v) : "l"(p) : "memory");
        if (v < target) __nanosleep(64);
    } while (v < target);
}
// release-ordered counter increment (pairs with ld.acquire spins; avoids MEMBAR.GPU)
__device__ __forceinline__ void release_add(unsigned* p, unsigned v) {
    asm volatile("red.release.gpu.global.add.u32 [%0], %1;" :: "l"(p), "r"(v) : "memory");
}

// ---------------------------------------------------------------------------
// reset kernel (tiny; kernel boundary orders it before mega)
// ---------------------------------------------------------------------------
__global__ void reset_kernel() {
    const int i = threadIdx.x;   // 512 threads
    if (i < B_ * 8)  ((unsigned*)g_cnt)[i] = 0u;
    if (i < E_ * 16) g_w1c[i] = 0u;
    if (i < E_ * 4)  g_w2c[i] = 0u;
    if (i < B_)      { g_poolc[i] = 0u; g_gatef[i] = 0u; }
}

// ---------------------------------------------------------------------------
// GEMM core macros: 256 threads, 8 warps 2(m)x4(n), warp tile 64x32
// A/B tiles: 128 rows x 128B, XOR-swizzled: chunk_phys = chunk ^ (row&7)
// ---------------------------------------------------------------------------
#define ISSUE_STAGE_A(slot, A_SRC) do {                                        \
    const uint32_t _as = sm_base + (slot) * STAGE_BYTES;                       \
    _Pragma("unroll")                                                          \
    for (int _i = 0; _i < 4; _i++) {                                           \
        const int _c = _i * 256 + tid;                                         \
        const int _r = _c >> 3, _lc = _c & 7;                                  \
        cp16(_as + _r * 128 + ((_lc ^ (_r & 7)) << 4), (A_SRC(_r, _lc)));      \
    }                                                                          \
} while (0)

#define ISSUE_STAGE_B(slot, B_SRC) do {                                        \
    const uint32_t _bs = sm_base + (slot) * STAGE_BYTES + A_BYTES;             \
    _Pragma("unroll")                                                          \
    for (int _i = 0; _i < 4; _i++) {                                           \
        const int _c = _i * 256 + tid;                                         \
        const int _r = _c >> 3, _lc = _c & 7;                                  \
        cp16(_bs + _r * 128 + ((_lc ^ (_r & 7)) << 4), (B_SRC(_r, _lc)));      \
    }                                                                          \
} while (0)

#define ISSUE_STAGE(slot, A_SRC, B_SRC) do {                                   \
    ISSUE_STAGE_A(slot, A_SRC);                                                \
    ISSUE_STAGE_B(slot, B_SRC);                                                \
} while (0)

#define COMPUTE_STAGE(slot) do {                                               \
    const uint32_t _ab = sm_base + (slot) * STAGE_BYTES;                       \
    const uint32_t _bb = _ab + A_BYTES;                                        \
    _Pragma("unroll")                                                          \
    for (int ks = 0; ks < 4; ks++) {                                           \
        unsigned af[4][4], bf[4][2];                                           \
        _Pragma("unroll")                                                      \
        for (int mt = 0; mt < 4; mt++)                                         \
            ldsm_x4(af[mt][0], af[mt][1], af[mt][2], af[mt][3],                \
                    _ab + arow_off + mt * 2048 + (((2 * ks + ac) ^ sxor) << 4)); \
        _Pragma("unroll")                                                      \
        for (int nt = 0; nt < 4; nt++)                                         \
            ldsm_x2(bf[nt][0], bf[nt][1],                                      \
                    _bb + brow_off + nt * 1024 + (((2 * ks + bc) ^ sxor) << 4)); \
        _Pragma("unroll")                                                      \
        for (int mt = 0; mt < 4; mt++)                                         \
            _Pragma("unroll")                                                  \
            for (int nt = 0; nt < 4; nt++)                                     \
                mma_f16(acc[mt][nt], af[mt], bf[nt]);                          \
    }                                                                          \
} while (0)

// mainloop shared by both gemms (prologue handled by caller)
#define GEMM_MAINLOOP(NK, A_SRC, B_SRC) do {                                   \
    for (int kt = 0; kt < (NK); kt++) {                                        \
        cp_wait<STAGES - 2>();                                                 \
        __syncthreads();                                                       \
        const int pf = kt + STAGES - 1;                                        \
        if (pf < (NK)) {                                                       \
            const int kk = pf;                                                 \
            ISSUE_STAGE(pf % STAGES, A_SRC, B_SRC);                            \
        }                                                                      \
        cp_commit();                                                           \
        COMPUTE_STAGE(kt % STAGES);                                            \
    }                                                                          \
} while (0)

#define GEMM_PIPELINE(NK, A_SRC, B_SRC) do {                                   \
    _Pragma("unroll")                                                          \
    for (int s = 0; s < STAGES - 1; s++) {                                     \
        const int kk = s;                                                      \
        ISSUE_STAGE(s, A_SRC, B_SRC);                                          \
        cp_commit();                                                           \
    }                                                                          \
    GEMM_MAINLOOP(NK, A_SRC, B_SRC);                                           \
} while (0)

#define LANE_OFFS()                                                            \
    const int wm = (warp & 1) * 64;                                            \
    const int wn = (warp >> 1) * 32;                                           \
    const uint32_t arow_off = (uint32_t)(wm + (lane & 15)) * 128;              \
    const uint32_t ac = (uint32_t)(lane >> 4);                                 \
    const uint32_t brow_off = (uint32_t)(wn + (lane & 7)) * 128;               \
    const uint32_t bc = (uint32_t)((lane >> 3) & 1);                           \
    const uint32_t sxor = (uint32_t)(lane & 7);

// ---------------------------------------------------------------------------
// MEGA kernel: [pool+gate | w1t | w2t | gemm1 | gemm2]  (dynamic smem ONLY)
// ---------------------------------------------------------------------------
__global__ __launch_bounds__(256, 2) void mega_kernel(
        const float* __restrict__ x,  const float* __restrict__ gw,
        const float* __restrict__ gb, const float* __restrict__ w1,
        const float* __restrict__ b1, const float* __restrict__ w2,
        const float* __restrict__ b2, float* __restrict__ out,
        float* __restrict__ out_logits) {
    extern __shared__ char smem[];
    const int bid = blockIdx.x;
    const int tid = threadIdx.x;

    if (bid < NB_POOL) {
        // -------- pool + x->fp16; 8th block per batch computes gate --------
        const int b = bid >> 3, ch = bid & 7;
        const size_t rbase = ((size_t)b * T_ + (size_t)ch * 128) * D_;
        #pragma unroll
        for (int half = 0; half < 2; half++) {
            const int d = tid + half * 256;
            float s = 0.f;
            for (int t = 0; t < 128; t++) {
                float v = x[rbase + (size_t)t * D_ + d];
                s += v;
                g_xh[rbase + (size_t)t * D_ + d] = __float2half_rn(v);
            }
            g_pool[b][ch][d] = s;
        }
        int* is_last = (int*)smem;
        __syncthreads();
        if (tid == 0) {
            __threadfence();
            *is_last = (atomicAdd(&g_poolc[b], 1u) == 7u) ? 1 : 0;
        }
        __syncthreads();
        if (*is_last) {
            __threadfence();
            float* pooled = (float*)smem + 16;     // 512 floats
            float* logits = pooled + 512;          // 8 floats
            #pragma unroll
            for (int half = 0; half < 2; half++) {
                const int d = tid + half * 256;
                float s = 0.f;
                #pragma unroll
                for (int c = 0; c < 8; c++) s += g_pool[b][c][d];
                pooled[d] = s * (1.0f / (float)T_);
            }
            __syncthreads();
            const int w = tid >> 5, lane = tid & 31;
            if (w < E_) {
                float acc = 0.f;
                for (int j = lane; j < D_; j += 32)
                    acc += pooled[j] * gw[(size_t)j * E_ + w];
                #pragma unroll
                for (int o = 16; o > 0; o >>= 1)
                    acc += __shfl_xor_sync(0xffffffffu, acc, o);
                if (lane == 0) logits[w] = acc + gb[w];
            }
            __syncthreads();
            if (tid == 0) {
                int i0 = 0; float l0 = logits[0];
                #pragma unroll
                for (int e = 1; e < E_; e++) if (logits[e] > l0) { l0 = logits[e]; i0 = e; }
                int i1 = -1; float l1 = -1e30f;
                #pragma unroll
                for (int e = 0; e < E_; e++)
                    if (e != i0 && logits[e] > l1) { l1 = logits[e]; i1 = e; }
                float e1 = expf(l1 - l0);
                float inv = 1.0f / (1.0f + e1);
                g_eidx[b][0] = i0; g_eidx[b][1] = i1;
                g_prob[b][0] = inv; g_prob[b][1] = e1 * inv;
                #pragma unroll
                for (int e = 0; e < E_; e++) out_logits[b * E_ + e] = logits[e];
                release_add(&g_gatef[b], 1u);
            }
        }
        return;
    }
    if (bid < OFF_W2T) {
        // -------- w1 transpose: [E][D][H] -> [E][H][D]  (dyn smem tile) ----
        float* tile = (float*)smem;                 // [64][65]
        const int idx = bid - OFF_W1T;
        const int e = idx >> 8, cx = idx & 31, cy = (idx >> 5) & 7;
        const float* S = w1 + (size_t)e * D_ * H_;
        __half* Dp = g_w1t + (size_t)e * H_ * D_;
        const int r0 = cy * 64, c0 = cx * 64;
        const int tx = tid & 63, ty = tid >> 6;     // ty 0..3
        #pragma unroll
        for (int i = 0; i < 16; i++) {
            const int row = ty + i * 4;
            tile[row * 65 + tx] = S[(size_t)(r0 + row) * H_ + c0 + tx];
        }
        __syncthreads();
        #pragma unroll
        for (int i = 0; i < 16; i++) {
            const int row = ty + i * 4;
            Dp[(size_t)(c0 + row) * D_ + r0 + tx] = __float2half_rn(tile[tx * 65 + row]);
        }
        __syncthreads();
        if (tid == 0) release_add(&g_w1c[e * 16 + (cx >> 1)], 1u);
        return;
    }
    if (bid < OFF_G1) {
        // -------- w2 transpose: [E][H][D] -> [E][D][H] ----------------------
        float* tile = (float*)smem;
        const int idx = bid - OFF_W2T;
        const int e = idx >> 8, cx = idx & 7, cy = (idx >> 3) & 31;
        const float* S = w2 + (size_t)e * H_ * D_;
        __half* Dp = g_w2t + (size_t)e * D_ * H_;
        const int r0 = cy * 64, c0 = cx * 64;
        const int tx = tid & 63, ty = tid >> 6;
        #pragma unroll
        for (int i = 0; i < 16; i++) {
            const int row = ty + i * 4;
            tile[row * 65 + tx] = S[(size_t)(r0 + row) * D_ + c0 + tx];
        }
        __syncthreads();
        #pragma unroll
        for (int i = 0; i < 16; i++) {
            const int row = ty + i * 4;
            Dp[(size_t)(c0 + row) * H_ + r0 + tx] = __float2half_rn(tile[tx * 65 + row]);
        }
        __syncthreads();
        if (tid == 0) release_add(&g_w2c[e * 4 + (cx >> 1)], 1u);
        return;
    }

    // ======================= GEMM paths =======================
    const uint32_t sm_base = smem_u32(smem);
    const int warp = tid >> 5, lane = tid & 31;
    LANE_OFFS();
    const int g = lane >> 2, t4 = lane & 3;

    float acc[4][4][4];
    #pragma unroll
    for (int i = 0; i < 4; i++)
        #pragma unroll
        for (int j = 0; j < 4; j++)
            #pragma unroll
            for (int r = 0; r < 4; r++) acc[i][j][r] = 0.f;

    if (bid < OFF_G2) {
        // =============== GEMM1 ===============
        const int v = bid - OFF_G1;
        const int xt = v & 15, yt = (v >> 4) & 7, bz = v >> 7;
        const int b = bz >> 1, slot = bz & 1;
        const int m0 = yt * BM, n0 = xt * BN;

        const __half* Ag = g_xh + ((size_t)b * T_ + m0) * D_;
        #define A1(r, c) (Ag + (size_t)(r) * D_ + kk * BK + (c) * 8)

        // prefetch A stages 0,1 BEFORE dependency spins (A needs no gate/e)
        {
            { const int kk = 0; ISSUE_STAGE_A(0, A1); }
            { const int kk = 1; ISSUE_STAGE_A(1, A1); }
        }

        if (tid == 0) spin_ge(&g_gatef[b], 1u);
        __syncthreads();
        const int e = g_eidx[b][slot];
        const float p = g_prob[b][slot];
        if (tid == 0) spin_ge(&g_w1c[e * 16 + xt], 16u);
        __syncthreads();

        const __half* Bg = g_w1t + ((size_t)e * H_ + n0) * D_;
        #define B1(r, c) (Bg + (size_t)(r) * D_ + kk * BK + (c) * 8)

        // finish prologue: B for stages 0,1 (group0 = A0,A1,B0; group1 = B1)
        { const int kk = 0; ISSUE_STAGE_B(0, B1); }
        cp_commit();
        { const int kk = 1; ISSUE_STAGE_B(1, B1); }
        cp_commit();

        GEMM_MAINLOOP(D_ / BK, A1, B1);      // 8 k-tiles
        #undef A1
        #undef B1

        const float* brow = b1 + (size_t)e * H_ + n0;
        __half* Hb = g_h + ((size_t)b * T_ + m0) * (2 * H_) + (size_t)slot * H_ + n0;
        #pragma unroll
        for (int mt = 0; mt < 4; mt++) {
            #pragma unroll
            for (int nt = 0; nt < 4; nt++) {
                #pragma unroll
                for (int half = 0; half < 2; half++) {
                    const int row = wm + mt * 16 + g + half * 8;
                    const int col = wn + nt * 8 + t4 * 2;
                    float v0 = acc[mt][nt][half * 2 + 0] + brow[col];
                    float v1 = acc[mt][nt][half * 2 + 1] + brow[col + 1];
                    v0 = p * v0 * (1.0f / (1.0f + __expf(-v0)));
                    v1 = p * v1 * (1.0f / (1.0f + __expf(-v1)));
                    *(__half2*)&Hb[(size_t)row * (2 * H_) + col] =
                        __floats2half2_rn(v0, v1);
                }
            }
        }
        __syncthreads();
        if (tid == 0) release_add(&g_cnt[b][yt], 1u);
    } else {
        // =============== GEMM2 ===============
        const int r2 = bid - OFF_G2;
        const int xt = r2 & 3, yt = (r2 >> 2) & 7, b = r2 >> 5;
        const int m0 = yt * BM, n0 = xt * BN;

        if (tid == 0) spin_ge(&g_cnt[b][yt], 32u);
        __syncthreads();
        const int e0 = g_eidx[b][0], e1 = g_eidx[b][1];
        const float p0 = g_prob[b][0], p1 = g_prob[b][1];
        if (tid == 0) {
            spin_ge(&g_w2c[e0 * 4 + xt], 64u);
            spin_ge(&g_w2c[e1 * 4 + xt], 64u);
        }
        __syncthreads();

        const __half* Ag  = g_h + ((size_t)b * T_ + m0) * (2 * H_);
        const __half* Bg0 = g_w2t + ((size_t)e0 * D_ + n0) * H_;
        const __half* Bg1 = g_w2t + ((size_t)e1 * D_ + n0) * H_;

        #define A2(r, c) (Ag + (size_t)(r) * (2 * H_) + kk * BK + (c) * 8)
        #define B2(r, c) ((kk < 32 ? Bg0 : Bg1) + (size_t)(r) * H_ + (kk & 31) * BK + (c) * 8)
        GEMM_PIPELINE((2 * H_) / BK, A2, B2);    // 64 k-tiles
        #undef A2
        #undef B2

        const float* b2r0 = b2 + (size_t)e0 * D_ + n0;
        const float* b2r1 = b2 + (size_t)e1 * D_ + n0;
        const float* xb = x   + ((size_t)b * T_ + m0) * D_ + n0;
        float*       ob = out + ((size_t)b * T_ + m0) * D_ + n0;
        #pragma unroll
        for (int mt = 0; mt < 4; mt++) {
            #pragma unroll
            for (int nt = 0; nt < 4; nt++) {
                #pragma unroll
                for (int half = 0; half < 2; half++) {
                    const int row = wm + mt * 16 + g + half * 8;
                    const int col = wn + nt * 8 + t4 * 2;
                    const float bias0 = p0 * b2r0[col]     + p1 * b2r1[col];
                    const float bias1 = p0 * b2r0[col + 1] + p1 * b2r1[col + 1];
                    const float2 xv = *(const float2*)&xb[(size_t)row * D_ + col];
                    float v0 = acc[mt][nt][half * 2 + 0] + bias0 + xv.x;
                    float v1 = acc[mt][nt][half * 2 + 1] + bias1 + xv.y;
                    *(float2*)&ob[(size_t)row * D_ + col] = make_float2(v0, v1);
                }
            }
        }
    }
}

// ---------------------------------------------------------------------------
extern "C" void kernel_launch(void* const* d_in, const int* in_sizes, int n_in,
                              void* d_out, int out_size) {
    const float* x  = (const float*)d_in[0];
    const float* gw = (const float*)d_in[1];
    const float* gb = (const float*)d_in[2];
    const float* w1 = (const float*)d_in[3];
    const float* b1 = (const float*)d_in[4];
    const float* w2 = (const float*)d_in[5];
    const float* b2 = (const float*)d_in[6];

    float* out = (float*)d_out;
    float* out_logits = out + (size_t)B_ * T_ * D_;

    cudaFuncSetAttribute(mega_kernel, cudaFuncAttributeMaxDynamicSharedMemorySize, SMEMSZ);

    reset_kernel<<<1, 512>>>();
    mega_kernel<<<NB_ALL, 256, SMEMSZ>>>(x, gw, gb, w1, b1, w2, b2, out, out_logits);
}